// round 13
// baseline (speedup 1.0000x reference)
#include <cuda_runtime.h>
#include <cstdint>
#include <cstddef>

// ---------------------------------------------------------------- constants
#define B_   8
#define NL_  64
#define NT_  512
#define H_   128
#define E_   2048
#define M_   4096
#define P_TOT (B_*NL_*NT_)          // 262144 pairs

#define OUT_PI 0
#define OUT_SG (P_TOT*10)
#define OUT_MU (P_TOT*20)
#define OUT_CB (P_TOT*30)
#define OUT_AT (OUT_CB + P_TOT)
#define OUT_BT (OUT_AT + 512*18)
#define OUT_CD (OUT_BT + E_*5)
#define OUT_CM (OUT_CD + M_)

// ---------------------------------------------------------------- scratch
__device__ float g_Lh[512*128];     // lig @ W_top, BN folded
__device__ float g_ThT[128*4096];   // (pro @ W_bot)*s, TRANSPOSED [h][ti]
__device__ float g_Ls[512*128];     // selector lig part
__device__ float g_Ts[4096*128];    // selector pro part

// ---------------------------------------------------------------- helpers
__device__ __forceinline__ float eluf(float x) {
    return fmaxf(x, 0.f) + __expf(fminf(x, 0.f)) - 1.f;
}
__device__ __forceinline__ float2 ffma2(float2 a, float2 b, float2 c) {
    float2 d;
    asm("fma.rn.f32x2 %0, %1, %2, %3;"
        : "=l"(reinterpret_cast<unsigned long long&>(d))
        : "l"(reinterpret_cast<unsigned long long&>(a)),
          "l"(reinterpret_cast<unsigned long long&>(b)),
          "l"(reinterpret_cast<unsigned long long&>(c)));
    return d;
}
__device__ __forceinline__ float2 fadd2(float2 a, float2 b) {
    float2 d;
    asm("add.rn.f32x2 %0, %1, %2;"
        : "=l"(reinterpret_cast<unsigned long long&>(d))
        : "l"(reinterpret_cast<unsigned long long&>(a)),
          "l"(reinterpret_cast<unsigned long long&>(b)));
    return d;
}

// ================================================================ FRONT kernel
#define FRONT_BLOCKS 352

__device__ __forceinline__ void gemm64(
    const float* __restrict__ A, const float* __restrict__ W, int ldw, int wrow0, int N,
    int r0, int c0, int mode,
    const float* __restrict__ g, const float* __restrict__ be,
    const float* __restrict__ m, const float* __restrict__ v,
    const float* __restrict__ lb,
    float* __restrict__ C, int ldc, int transC,
    float (*Ast)[68], float (*Ws)[68]) {

    int tid = threadIdx.x;
    int tx = tid & 15, ty = tid >> 4;
    float2 acc2[4][2] = {};

    for (int kc = 0; kc < 128; kc += 64) {
        #pragma unroll
        for (int q = tid; q < 64 * 16; q += 256) {
            int r = q >> 4, k4 = q & 15;
            float4 val = *(const float4*)(A + (size_t)(r0 + r) * 128 + kc + k4 * 4);
            Ast[k4 * 4 + 0][r] = val.x;
            Ast[k4 * 4 + 1][r] = val.y;
            Ast[k4 * 4 + 2][r] = val.z;
            Ast[k4 * 4 + 3][r] = val.w;
        }
        #pragma unroll
        for (int q = tid; q < 64 * 64; q += 256) {
            int k = q >> 6, c = q & 63;
            float w = 0.f;
            if (c0 + c < N) w = W[(size_t)(wrow0 + kc + k) * ldw + c0 + c];
            Ws[k][c] = w;
        }
        __syncthreads();
        #pragma unroll 16
        for (int k = 0; k < 64; k++) {
            float4 a4 = *(const float4*)&Ast[k][ty * 4];
            float4 w4 = *(const float4*)&Ws[k][tx * 4];
            float2 wlo = make_float2(w4.x, w4.y);
            float2 whi = make_float2(w4.z, w4.w);
            float av[4] = {a4.x, a4.y, a4.z, a4.w};
            #pragma unroll
            for (int d = 0; d < 4; d++) {
                float2 ad = make_float2(av[d], av[d]);
                acc2[d][0] = ffma2(ad, wlo, acc2[d][0]);
                acc2[d][1] = ffma2(ad, whi, acc2[d][1]);
            }
        }
        __syncthreads();
    }

    #pragma unroll
    for (int e = 0; e < 4; e++) {
        int c = c0 + tx * 4 + e;
        if (c >= N) continue;
        float s = 1.f, cb = 0.f;
        if (mode == 0) {
            s = g[c] * rsqrtf(v[c] + 1e-5f);
            cb = (lb[c] - m[c]) * s + be[c];
        } else if (mode == 1) {
            s = g[c] * rsqrtf(v[c] + 1e-5f);
        } else {
            cb = lb[c];
        }
        #pragma unroll
        for (int d = 0; d < 4; d++) {
            int r = r0 + ty * 4 + d;
            float a = (e & 1) ? acc2[d][e >> 1].y : acc2[d][e >> 1].x;
            float val = a * s + cb;
            if (transC) C[(size_t)c * ldc + r] = val;
            else        C[(size_t)r * ldc + c] = val;
        }
    }
}

__global__ void __launch_bounds__(256)
front_kernel(const float* __restrict__ lig_s, const float* __restrict__ pro_s,
             const int* __restrict__ eidx,
             const float* __restrict__ mlp_w, const float* __restrict__ mlp_b,
             const float* __restrict__ mlp_g, const float* __restrict__ mlp_be,
             const float* __restrict__ mlp_m, const float* __restrict__ mlp_v,
             const float* __restrict__ sel_w1, const float* __restrict__ sel_b1,
             const float* __restrict__ sel_g, const float* __restrict__ sel_be,
             const float* __restrict__ sel_m, const float* __restrict__ sel_v,
             const float* __restrict__ at_w, const float* __restrict__ at_b,
             const float* __restrict__ bt_w, const float* __restrict__ bt_b,
             float* __restrict__ Lh, float* __restrict__ ThT,
             float* __restrict__ Ls, float* __restrict__ Ts,
             float* __restrict__ out) {
    __shared__ float Ast[64][68];
    __shared__ float Ws[64][68];
    int blk = blockIdx.x;
    int tid = threadIdx.x;

    if (blk < 16) {
        int i = blk;
        gemm64(lig_s, mlp_w, 128, 0, 128, (i >> 1) * 64, (i & 1) * 64, 0,
               mlp_g, mlp_be, mlp_m, mlp_v, mlp_b, Lh, 128, 0, Ast, Ws);
    } else if (blk < 32) {
        int i = blk - 16;
        gemm64(lig_s, sel_w1, 128, 0, 128, (i >> 1) * 64, (i & 1) * 64, 0,
               sel_g, sel_be, sel_m, sel_v, sel_b1, Ls, 128, 0, Ast, Ws);
    } else if (blk < 40) {
        int i = blk - 32;
        gemm64(lig_s, at_w, 18, 0, 18, i * 64, 0, 2,
               nullptr, nullptr, nullptr, nullptr, at_b, out + OUT_AT, 18, 0, Ast, Ws);
    } else if (blk < 168) {
        int i = blk - 40;
        gemm64(pro_s, mlp_w, 128, 128, 128, (i >> 1) * 64, (i & 1) * 64, 1,
               mlp_g, nullptr, nullptr, mlp_v, nullptr, ThT, 4096, 1, Ast, Ws);
    } else if (blk < 296) {
        int i = blk - 168;
        gemm64(pro_s, sel_w1, 128, 128, 128, (i >> 1) * 64, (i & 1) * 64, 1,
               sel_g, nullptr, nullptr, sel_v, nullptr, Ts, 128, 0, Ast, Ws);
    } else if (blk < 336) {
        int t = (blk - 296) * 256 + tid;
        if (t < E_ * 5) {
            int e = t / 5, c = t - e * 5;
            int e0 = eidx[e], e1 = eidx[E_ + e];
            float acc = bt_b[c];
            const float* r0 = lig_s + (size_t)e0 * 128;
            const float* r1 = lig_s + (size_t)e1 * 128;
            #pragma unroll 4
            for (int k = 0; k < 128; k++) acc = fmaf(r0[k], __ldg(bt_w + k * 5 + c), acc);
            #pragma unroll 4
            for (int k = 0; k < 128; k++) acc = fmaf(r1[k], __ldg(bt_w + (128 + k) * 5 + c), acc);
            out[OUT_BT + t] = acc;
        }
    } else {
        int base = (blk - 336) * 4096;
        float4* cb = (float4*)(out + OUT_CB);
        float4* cm = (float4*)(out + OUT_CM);
        const float4 ones = make_float4(1.f, 1.f, 1.f, 1.f);
        #pragma unroll
        for (int it = 0; it < 16; it++) {
            int q = base + it * 256 + tid;
            float b = (float)((q * 4) >> 15);
            cb[q] = make_float4(b, b, b, b);
            cm[q] = ones;
        }
    }
}

// ================================================================ BACK kernel
// blocks [0,256): pairwise MDN head. Tile 8 lig x 128 pro, 512 threads.
//   thread = (il 0..7, jq 0..31, kh 0..1): 4 pairs x 8 k-PAIRS, k-packed FFMA2.
//   elu computed WITHOUT the -1 (q = max(x,0)+exp(min(x,0))); the -1 is folded
//   into epilogue biases via column sums S_k = sum_h w[h,k]  (validated R7).
// blocks [256,272): donor selector.
// smem: Th 64KB | L 4KB | Wk 16KB | Sg 128B
#define SMEM_MAIN (128*128*4 + 8*128*4 + 128*16*8 + 128)
#define BACK_BLOCKS 272

__global__ void __launch_bounds__(512, 1)
back_kernel(const float* __restrict__ Lh, const float* __restrict__ ThT,
            const float* __restrict__ Ls, const float* __restrict__ Ts,
            const float* __restrict__ pi_w, const float* __restrict__ pi_b,
            const float* __restrict__ sg_w, const float* __restrict__ sg_b,
            const float* __restrict__ mu_w, const float* __restrict__ mu_b,
            const int* __restrict__ donar_idx,
            const float* __restrict__ sel_w2, const float* __restrict__ sel_b2,
            float* __restrict__ out) {
    int tid = threadIdx.x;
    int blk = blockIdx.x;

    if (blk >= 256) {
        // ---------------- donor selector: 16 blocks x 16 warps ----------------
        int w = tid >> 5, lane = tid & 31;
        float w2v[4];
        #pragma unroll
        for (int hq = 0; hq < 4; hq++) w2v[hq] = __ldg(sel_w2 + lane + hq * 32);
        float b2 = __ldg(sel_b2);
        #pragma unroll 2
        for (int it = 0; it < 16; it++) {
            int mm = (blk - 256) * 256 + it * 16 + w;
            int p = donar_idx[mm];
            int li = p / 512;
            int ti = (p >> 15) * 512 + (p & 511);
            float acc = 0.f;
            #pragma unroll
            for (int hq = 0; hq < 4; hq++) {
                int h = lane + hq * 32;
                float x = Ls[(size_t)li * 128 + h] + Ts[(size_t)ti * 128 + h];
                acc = fmaf(eluf(x), w2v[hq], acc);
            }
            #pragma unroll
            for (int o = 16; o; o >>= 1) acc += __shfl_xor_sync(0xffffffffu, acc, o);
            if (lane == 0) out[OUT_CD + mm] = 1.f / (1.f + __expf(-(acc + b2)));
        }
        return;
    }

    // ---------------- pairwise MDN ----------------
    extern __shared__ float sm[];
    float*  Th_s = sm;                           // [h][j] stride 128 (64KB)
    float*  L_s  = sm + 128 * 128;               // [il][h] (4KB)
    float2* Wk   = (float2*)(L_s + 8 * 128);     // [h][kp 0..15] (16KB)
    float*  Sg_s = (float*)(Wk + 128 * 16);      // column sums S[k 0..31]

    int jg = blk & 3;
    int ig = (blk >> 2) & 7;
    int b  = blk >> 5;
    int ti_base = b * 512 + jg * 128;
    int li_base = b * 64 + ig * 8;

    #pragma unroll
    for (int q = tid; q < 128 * 32; q += 512) {
        int h = q >> 5, j4 = q & 31;
        float4 v = *(const float4*)(ThT + (size_t)h * 4096 + ti_base + j4 * 4);
        *(float4*)&Th_s[h * 128 + j4 * 4] = v;
    }
    if (tid < 8 * 32) {
        int r = tid >> 5, k4 = tid & 31;
        *(float4*)&L_s[r * 128 + k4 * 4] =
            *(const float4*)(Lh + (size_t)(li_base + r) * 128 + k4 * 4);
    }
    // weights, k-pair packed: Wk[h*16+kp] = {w[2kp], w[2kp+1]}, k>=30 -> 0
    #pragma unroll
    for (int q = tid; q < 128 * 16; q += 512) {
        int h  = q >> 4;
        int kp = q & 15;
        float wv[2];
        #pragma unroll
        for (int c = 0; c < 2; c++) {
            int k = 2 * kp + c;
            wv[c] = (k < 10) ? pi_w[h * 10 + k]
                  : (k < 20) ? sg_w[h * 10 + k - 10]
                  : (k < 30) ? mu_w[h * 10 + k - 20]
                             : 0.f;
        }
        Wk[q] = make_float2(wv[0], wv[1]);
    }
    // column sums S[k] from global weights (warp 0)
    if (tid < 32) {
        float s = 0.f;
        if (tid < 30) {
            for (int h = 0; h < 128; h++) {
                s += (tid < 10) ? pi_w[h * 10 + tid]
                   : (tid < 20) ? sg_w[h * 10 + tid - 10]
                                : mu_w[h * 10 + tid - 20];
            }
        }
        Sg_s[tid] = s;
    }
    __syncthreads();

    int il = tid >> 6;
    int r6 = tid & 63;
    int jq = r6 >> 1;          // 0..31, pairs j = jq*4 .. +3
    int kh = r6 & 1;           // k half: kp 0..7 or 8..15

    const float4* Lrow4 = (const float4*)(L_s + il * 128);
    const float4* Tbase = (const float4*)Th_s + jq;            // + h*32
    const float4* Wbase = (const float4*)Wk + kh * 4;          // + h*8

    float2 a[4][8];            // [pair][kp]
    #pragma unroll
    for (int p = 0; p < 4; p++)
        #pragma unroll
        for (int k = 0; k < 8; k++) a[p][k] = make_float2(0.f, 0.f);

    #pragma unroll 2
    for (int h4 = 0; h4 < 32; h4++) {
        float4 lv4 = Lrow4[h4];
        float lvs[4] = {lv4.x, lv4.y, lv4.z, lv4.w};
        #pragma unroll
        for (int hh = 0; hh < 4; hh++) {
            int h = h4 * 4 + hh;
            float lv = lvs[hh];
            float4 t = Tbase[h * 32];
            float2 lv2 = make_float2(lv, lv);
            float2 x01 = fadd2(lv2, make_float2(t.x, t.y));
            float2 x23 = fadd2(lv2, make_float2(t.z, t.w));
            // q = max(x,0) + exp(min(x,0))   (-1 folded into epilogue via Sg)
            float2 p01 = make_float2(fmaf(0.f, x01.x, fmaxf(x01.x, 0.f)) + __expf(fminf(x01.x, 0.f)),
                                     fmaxf(x01.y, 0.f) + __expf(fminf(x01.y, 0.f)));
            p01.x = fmaxf(x01.x, 0.f) + __expf(fminf(x01.x, 0.f));
            float2 p23 = make_float2(fmaxf(x23.x, 0.f) + __expf(fminf(x23.x, 0.f)),
                                     fmaxf(x23.y, 0.f) + __expf(fminf(x23.y, 0.f)));
            float2 pd[4] = { make_float2(p01.x, p01.x), make_float2(p01.y, p01.y),
                             make_float2(p23.x, p23.x), make_float2(p23.y, p23.y) };
            const float4* wrow = Wbase + h * 8;
            float4 wv4[4];
            #pragma unroll
            for (int i = 0; i < 4; i++) wv4[i] = wrow[i];
            const float2* wk = (const float2*)wv4;   // 8 k-pairs
            #pragma unroll
            for (int p = 0; p < 4; p++)
                #pragma unroll
                for (int k = 0; k < 8; k++)
                    a[p][k] = ffma2(pd[p], wk[k], a[p][k]);
        }
    }

    int pair0 = (li_base + il) * 512 + jg * 128 + jq * 4;

    if (kh == 0) {
        // kp 0..4 -> pi[0..9]; kp 5..7 -> sg[0..5]   (global k 0..15)
        float pib[10], sgb6[6];
        #pragma unroll
        for (int k = 0; k < 10; k++) pib[k] = __ldg(pi_b + k) - Sg_s[k];
        #pragma unroll
        for (int k = 0; k < 6; k++) sgb6[k] = __ldg(sg_b + k) - Sg_s[10 + k];

        float obuf[40];
        #pragma unroll
        for (int jj = 0; jj < 4; jj++) {
            float v[10];
            #pragma unroll
            for (int k = 0; k < 10; k++) {
                float2 ak = a[jj][k >> 1];
                v[k] = ((k & 1) ? ak.y : ak.x) + pib[k];
            }
            float mx = v[0];
            #pragma unroll
            for (int k = 1; k < 10; k++) mx = fmaxf(mx, v[k]);
            float s = 0.f;
            #pragma unroll
            for (int k = 0; k < 10; k++) { v[k] = __expf(v[k] - mx); s += v[k]; }
            float inv = 1.0f / s;
            #pragma unroll
            for (int k = 0; k < 10; k++) obuf[jj * 10 + k] = v[k] * inv;
        }
        {
            float4* dst = (float4*)(out + OUT_PI + (size_t)pair0 * 10);
            #pragma unroll
            for (int q = 0; q < 10; q++) dst[q] = ((float4*)obuf)[q];
        }
        #pragma unroll
        for (int jj = 0; jj < 4; jj++) {
            float s6[6];
            #pragma unroll
            for (int si = 0; si < 6; si++) {
                float2 ak = a[jj][5 + (si >> 1)];
                float x = (si & 1) ? ak.y : ak.x;
                s6[si] = eluf(x + sgb6[si]) + 1.1f;
            }
            float* dst = out + OUT_SG + (size_t)(pair0 + jj) * 10;
            *(float2*)(dst + 0) = make_float2(s6[0], s6[1]);
            *(float2*)(dst + 2) = make_float2(s6[2], s6[3]);
            *(float2*)(dst + 4) = make_float2(s6[4], s6[5]);
        }
    } else {
        // kp 0..1 -> sg[6..9]; kp 2..6 -> mu[0..9]; kp 7 pad   (global k 16..31)
        float sgb4[4], mub[10];
        #pragma unroll
        for (int k = 0; k < 4; k++) sgb4[k] = __ldg(sg_b + 6 + k) - Sg_s[16 + k];
        #pragma unroll
        for (int k = 0; k < 10; k++) mub[k] = __ldg(mu_b + k) - Sg_s[20 + k];

        #pragma unroll
        for (int jj = 0; jj < 4; jj++) {
            float s4[4];
            #pragma unroll
            for (int si = 0; si < 4; si++) {
                float2 ak = a[jj][si >> 1];
                float x = (si & 1) ? ak.y : ak.x;
                s4[si] = eluf(x + sgb4[si]) + 1.1f;
            }
            float* dst = out + OUT_SG + (size_t)(pair0 + jj) * 10;
            *(float2*)(dst + 6) = make_float2(s4[0], s4[1]);
            *(float2*)(dst + 8) = make_float2(s4[2], s4[3]);
        }
        float obuf[40];
        #pragma unroll
        for (int jj = 0; jj < 4; jj++)
            #pragma unroll
            for (int mi = 0; mi < 10; mi++) {
                float2 ak = a[jj][2 + (mi >> 1)];
                float x = (mi & 1) ? ak.y : ak.x;
                obuf[jj * 10 + mi] = eluf(x + mub[mi]) + 1.0f;
            }
        {
            float4* dst = (float4*)(out + OUT_MU + (size_t)pair0 * 10);
            #pragma unroll
            for (int q = 0; q < 10; q++) dst[q] = ((float4*)obuf)[q];
        }
    }
}

// ================================================================ launch
extern "C" void kernel_launch(void* const* d_in, const int* in_sizes, int n_in,
                              void* d_out, int out_size) {
    const float* lig_s  = (const float*)d_in[0];
    const float* pro_s  = (const float*)d_in[1];
    const int*   donar  = (const int*)d_in[4];
    const int*   eidx   = (const int*)d_in[5];
    const float* mlp_w  = (const float*)d_in[6];
    const float* mlp_b  = (const float*)d_in[7];
    const float* mlp_g  = (const float*)d_in[8];
    const float* mlp_be = (const float*)d_in[9];
    const float* mlp_m  = (const float*)d_in[10];
    const float* mlp_v  = (const float*)d_in[11];
    const float* sel_w1 = (const float*)d_in[12];
    const float* sel_b1 = (const float*)d_in[13];
    const float* sel_g  = (const float*)d_in[14];
    const float* sel_be = (const float*)d_in[15];
    const float* sel_m  = (const float*)d_in[16];
    const float* sel_v  = (const float*)d_in[17];
    const float* sel_w2 = (const float*)d_in[18];
    const float* sel_b2 = (const float*)d_in[19];
    const float* pi_w   = (const float*)d_in[20];
    const float* pi_b   = (const float*)d_in[21];
    const float* sg_w   = (const float*)d_in[22];
    const float* sg_b   = (const float*)d_in[23];
    const float* mu_w   = (const float*)d_in[24];
    const float* mu_b   = (const float*)d_in[25];
    const float* at_w   = (const float*)d_in[26];
    const float* at_b   = (const float*)d_in[27];
    const float* bt_w   = (const float*)d_in[28];
    const float* bt_b   = (const float*)d_in[29];
    float* out = (float*)d_out;

    float *Lh, *ThT, *Ls, *Ts;
    cudaGetSymbolAddress((void**)&Lh,  g_Lh);
    cudaGetSymbolAddress((void**)&ThT, g_ThT);
    cudaGetSymbolAddress((void**)&Ls,  g_Ls);
    cudaGetSymbolAddress((void**)&Ts,  g_Ts);

    cudaFuncSetAttribute((const void*)back_kernel,
                         cudaFuncAttributeMaxDynamicSharedMemorySize, SMEM_MAIN);

    front_kernel<<<FRONT_BLOCKS, 256>>>(
        lig_s, pro_s, eidx,
        mlp_w, mlp_b, mlp_g, mlp_be, mlp_m, mlp_v,
        sel_w1, sel_b1, sel_g, sel_be, sel_m, sel_v,
        at_w, at_b, bt_w, bt_b,
        Lh, ThT, Ls, Ts, out);

    back_kernel<<<BACK_BLOCKS, 512, SMEM_MAIN>>>(
        Lh, ThT, Ls, Ts,
        pi_w, pi_b, sg_w, sg_b, mu_w, mu_b,
        donar, sel_w2, sel_b2, out);
}

// round 14
// speedup vs baseline: 1.1727x; 1.1727x over previous
#include <cuda_runtime.h>
#include <cstdint>
#include <cstddef>

// ---------------------------------------------------------------- constants
#define B_   8
#define NL_  64
#define NT_  512
#define H_   128
#define E_   2048
#define M_   4096
#define P_TOT (B_*NL_*NT_)          // 262144 pairs

// output layout: tuple flattened in return order, float32
#define OUT_PI 0
#define OUT_SG (P_TOT*10)
#define OUT_MU (P_TOT*20)
#define OUT_CB (P_TOT*30)
#define OUT_AT (OUT_CB + P_TOT)
#define OUT_BT (OUT_AT + 512*18)
#define OUT_CD (OUT_BT + E_*5)
#define OUT_CM (OUT_CD + M_)

// ---------------------------------------------------------------- scratch
__device__ float g_Lh[512*128];     // lig @ W_top, BN folded
__device__ float g_ThT[128*4096];   // (pro @ W_bot)*s, TRANSPOSED [h][ti]
__device__ float g_Ls[512*128];     // selector lig part
__device__ float g_Ts[4096*128];    // selector pro part

// ---------------------------------------------------------------- helpers
__device__ __forceinline__ float eluf(float x) {
    return fmaxf(x, 0.f) + __expf(fminf(x, 0.f)) - 1.f;
}
__device__ __forceinline__ float2 ffma2(float2 a, float2 b, float2 c) {
    float2 d;
    asm("fma.rn.f32x2 %0, %1, %2, %3;"
        : "=l"(reinterpret_cast<unsigned long long&>(d))
        : "l"(reinterpret_cast<unsigned long long&>(a)),
          "l"(reinterpret_cast<unsigned long long&>(b)),
          "l"(reinterpret_cast<unsigned long long&>(c)));
    return d;
}
__device__ __forceinline__ float2 fadd2(float2 a, float2 b) {
    float2 d;
    asm("add.rn.f32x2 %0, %1, %2;"
        : "=l"(reinterpret_cast<unsigned long long&>(d))
        : "l"(reinterpret_cast<unsigned long long&>(a)),
          "l"(reinterpret_cast<unsigned long long&>(b)));
    return d;
}

// ================================================================ FRONT kernel
#define FRONT_BLOCKS 352

__device__ __forceinline__ void gemm64(
    const float* __restrict__ A, const float* __restrict__ W, int ldw, int wrow0, int N,
    int r0, int c0, int mode,
    const float* __restrict__ g, const float* __restrict__ be,
    const float* __restrict__ m, const float* __restrict__ v,
    const float* __restrict__ lb,
    float* __restrict__ C, int ldc, int transC,
    float (*Ast)[68], float (*Ws)[68]) {

    int tid = threadIdx.x;
    int tx = tid & 15, ty = tid >> 4;
    float2 acc2[4][2] = {};

    for (int kc = 0; kc < 128; kc += 64) {
        #pragma unroll
        for (int q = tid; q < 64 * 16; q += 256) {
            int r = q >> 4, k4 = q & 15;
            float4 val = *(const float4*)(A + (size_t)(r0 + r) * 128 + kc + k4 * 4);
            Ast[k4 * 4 + 0][r] = val.x;
            Ast[k4 * 4 + 1][r] = val.y;
            Ast[k4 * 4 + 2][r] = val.z;
            Ast[k4 * 4 + 3][r] = val.w;
        }
        #pragma unroll
        for (int q = tid; q < 64 * 64; q += 256) {
            int k = q >> 6, c = q & 63;
            float w = 0.f;
            if (c0 + c < N) w = W[(size_t)(wrow0 + kc + k) * ldw + c0 + c];
            Ws[k][c] = w;
        }
        __syncthreads();
        #pragma unroll 16
        for (int k = 0; k < 64; k++) {
            float4 a4 = *(const float4*)&Ast[k][ty * 4];
            float4 w4 = *(const float4*)&Ws[k][tx * 4];
            float2 wlo = make_float2(w4.x, w4.y);
            float2 whi = make_float2(w4.z, w4.w);
            float av[4] = {a4.x, a4.y, a4.z, a4.w};
            #pragma unroll
            for (int d = 0; d < 4; d++) {
                float2 ad = make_float2(av[d], av[d]);
                acc2[d][0] = ffma2(ad, wlo, acc2[d][0]);
                acc2[d][1] = ffma2(ad, whi, acc2[d][1]);
            }
        }
        __syncthreads();
    }

    #pragma unroll
    for (int e = 0; e < 4; e++) {
        int c = c0 + tx * 4 + e;
        if (c >= N) continue;
        float s = 1.f, cb = 0.f;
        if (mode == 0) {
            s = g[c] * rsqrtf(v[c] + 1e-5f);
            cb = (lb[c] - m[c]) * s + be[c];
        } else if (mode == 1) {
            s = g[c] * rsqrtf(v[c] + 1e-5f);
        } else {
            cb = lb[c];
        }
        #pragma unroll
        for (int d = 0; d < 4; d++) {
            int r = r0 + ty * 4 + d;
            float a = (e & 1) ? acc2[d][e >> 1].y : acc2[d][e >> 1].x;
            float val = a * s + cb;
            if (transC) C[(size_t)c * ldc + r] = val;
            else        C[(size_t)r * ldc + c] = val;
        }
    }
}

__global__ void __launch_bounds__(256)
front_kernel(const float* __restrict__ lig_s, const float* __restrict__ pro_s,
             const int* __restrict__ eidx,
             const float* __restrict__ mlp_w, const float* __restrict__ mlp_b,
             const float* __restrict__ mlp_g, const float* __restrict__ mlp_be,
             const float* __restrict__ mlp_m, const float* __restrict__ mlp_v,
             const float* __restrict__ sel_w1, const float* __restrict__ sel_b1,
             const float* __restrict__ sel_g, const float* __restrict__ sel_be,
             const float* __restrict__ sel_m, const float* __restrict__ sel_v,
             const float* __restrict__ at_w, const float* __restrict__ at_b,
             const float* __restrict__ bt_w, const float* __restrict__ bt_b,
             float* __restrict__ Lh, float* __restrict__ ThT,
             float* __restrict__ Ls, float* __restrict__ Ts,
             float* __restrict__ out) {
    __shared__ float Ast[64][68];
    __shared__ float Ws[64][68];
    int blk = blockIdx.x;
    int tid = threadIdx.x;

    if (blk < 16) {
        int i = blk;
        gemm64(lig_s, mlp_w, 128, 0, 128, (i >> 1) * 64, (i & 1) * 64, 0,
               mlp_g, mlp_be, mlp_m, mlp_v, mlp_b, Lh, 128, 0, Ast, Ws);
    } else if (blk < 32) {
        int i = blk - 16;
        gemm64(lig_s, sel_w1, 128, 0, 128, (i >> 1) * 64, (i & 1) * 64, 0,
               sel_g, sel_be, sel_m, sel_v, sel_b1, Ls, 128, 0, Ast, Ws);
    } else if (blk < 40) {
        int i = blk - 32;
        gemm64(lig_s, at_w, 18, 0, 18, i * 64, 0, 2,
               nullptr, nullptr, nullptr, nullptr, at_b, out + OUT_AT, 18, 0, Ast, Ws);
    } else if (blk < 168) {
        int i = blk - 40;
        gemm64(pro_s, mlp_w, 128, 128, 128, (i >> 1) * 64, (i & 1) * 64, 1,
               mlp_g, nullptr, nullptr, mlp_v, nullptr, ThT, 4096, 1, Ast, Ws);
    } else if (blk < 296) {
        int i = blk - 168;
        gemm64(pro_s, sel_w1, 128, 128, 128, (i >> 1) * 64, (i & 1) * 64, 1,
               sel_g, nullptr, nullptr, sel_v, nullptr, Ts, 128, 0, Ast, Ws);
    } else if (blk < 336) {
        int t = (blk - 296) * 256 + tid;
        if (t < E_ * 5) {
            int e = t / 5, c = t - e * 5;
            int e0 = eidx[e], e1 = eidx[E_ + e];
            float acc = bt_b[c];
            const float* r0 = lig_s + (size_t)e0 * 128;
            const float* r1 = lig_s + (size_t)e1 * 128;
            #pragma unroll 4
            for (int k = 0; k < 128; k++) acc = fmaf(r0[k], __ldg(bt_w + k * 5 + c), acc);
            #pragma unroll 4
            for (int k = 0; k < 128; k++) acc = fmaf(r1[k], __ldg(bt_w + (128 + k) * 5 + c), acc);
            out[OUT_BT + t] = acc;
        }
    } else {
        int base = (blk - 336) * 4096;
        float4* cb = (float4*)(out + OUT_CB);
        float4* cm = (float4*)(out + OUT_CM);
        const float4 ones = make_float4(1.f, 1.f, 1.f, 1.f);
        #pragma unroll
        for (int it = 0; it < 16; it++) {
            int q = base + it * 256 + tid;
            float b = (float)((q * 4) >> 15);
            cb[q] = make_float4(b, b, b, b);
            cm[q] = ones;
        }
    }
}

// ================================================================ BACK kernel
// blocks [0,256): pairwise MDN head. Tile 8 lig x 128 pro, 512 threads.
//   thread = (il 0..7, jq 0..31, kh 0..1): 4 pairs x 8 k-PAIRS
//   k-packed FFMA2: acc{k,k+1} += {p,p} * {w_k, w_k+1}   (no weight duplication)
//   kh0 -> heads k 0..15 (pi[0..9], sg[0..5]); kh1 -> k 16..31 (sg[6..9], mu[0..9], pad)
// blocks [256,272): donor selector
// smem: Th 64KB + L 4KB + Wk 16KB = 84KB
#define SMEM_MAIN (128*128*4 + 8*128*4 + 128*16*8)
#define BACK_BLOCKS 272

__global__ void __launch_bounds__(512, 1)
back_kernel(const float* __restrict__ Lh, const float* __restrict__ ThT,
            const float* __restrict__ Ls, const float* __restrict__ Ts,
            const float* __restrict__ pi_w, const float* __restrict__ pi_b,
            const float* __restrict__ sg_w, const float* __restrict__ sg_b,
            const float* __restrict__ mu_w, const float* __restrict__ mu_b,
            const int* __restrict__ donar_idx,
            const float* __restrict__ sel_w2, const float* __restrict__ sel_b2,
            float* __restrict__ out) {
    int tid = threadIdx.x;
    int blk = blockIdx.x;

    if (blk >= 256) {
        // ---------------- donor selector ----------------
        int w = tid >> 5, lane = tid & 31;
        float w2v[4];
        #pragma unroll
        for (int hq = 0; hq < 4; hq++) w2v[hq] = __ldg(sel_w2 + lane + hq * 32);
        float b2 = __ldg(sel_b2);
        #pragma unroll 2
        for (int it = 0; it < 16; it++) {
            int mm = (blk - 256) * 256 + it * 16 + w;
            int p = donar_idx[mm];
            int li = p / 512;
            int ti = (p >> 15) * 512 + (p & 511);
            float acc = 0.f;
            #pragma unroll
            for (int hq = 0; hq < 4; hq++) {
                int h = lane + hq * 32;
                float x = Ls[(size_t)li * 128 + h] + Ts[(size_t)ti * 128 + h];
                acc = fmaf(eluf(x), w2v[hq], acc);
            }
            #pragma unroll
            for (int o = 16; o; o >>= 1) acc += __shfl_xor_sync(0xffffffffu, acc, o);
            if (lane == 0) out[OUT_CD + mm] = 1.f / (1.f + __expf(-(acc + b2)));
        }
        return;
    }

    // ---------------- pairwise MDN ----------------
    extern __shared__ float sm[];
    float*  Th_s = sm;                           // [h][j] stride 128 (64KB)
    float*  L_s  = sm + 128 * 128;               // [il][h] (4KB)
    float2* Wk   = (float2*)(L_s + 8 * 128);     // [h][kp 0..15] = {w[2kp],w[2kp+1]} (16KB)

    int jg = blk & 3;
    int ig = (blk >> 2) & 7;
    int b  = blk >> 5;
    int ti_base = b * 512 + jg * 128;
    int li_base = b * 64 + ig * 8;

    #pragma unroll
    for (int q = tid; q < 128 * 32; q += 512) {
        int h = q >> 5, j4 = q & 31;
        float4 v = *(const float4*)(ThT + (size_t)h * 4096 + ti_base + j4 * 4);
        *(float4*)&Th_s[h * 128 + j4 * 4] = v;
    }
    if (tid < 8 * 32) {
        int r = tid >> 5, k4 = tid & 31;
        *(float4*)&L_s[r * 128 + k4 * 4] =
            *(const float4*)(Lh + (size_t)(li_base + r) * 128 + k4 * 4);
    }
    // weights, k-pair packed, NOT duplicated: Wk[h*16+kp] = {w[2kp], w[2kp+1]}, k>=30 -> 0
    #pragma unroll
    for (int q = tid; q < 128 * 16; q += 512) {
        int h  = q >> 4;
        int kp = q & 15;
        float wv[2];
        #pragma unroll
        for (int c = 0; c < 2; c++) {
            int k = 2 * kp + c;
            wv[c] = (k < 10) ? pi_w[h * 10 + k]
                  : (k < 20) ? sg_w[h * 10 + k - 10]
                  : (k < 30) ? mu_w[h * 10 + k - 20]
                             : 0.f;
        }
        Wk[q] = make_float2(wv[0], wv[1]);
    }
    __syncthreads();

    int il = tid >> 6;
    int r6 = tid & 63;
    int jq = r6 >> 1;          // 0..31, pairs j = jq*4 .. +3
    int kh = r6 & 1;           // k half: kp 0..7 or 8..15

    const float4* Lrow4 = (const float4*)(L_s + il * 128);
    const float4* Tbase = (const float4*)Th_s + jq;            // + h*32
    const float4* Wbase = (const float4*)Wk + kh * 4;          // + h*8, 4 float4 = 8 float2

    float2 a[4][8];            // [pair][kp]
    #pragma unroll
    for (int p = 0; p < 4; p++)
        #pragma unroll
        for (int k = 0; k < 8; k++) a[p][k] = make_float2(0.f, 0.f);

    const float2 neg1 = make_float2(-1.f, -1.f);

    #pragma unroll 2
    for (int h4 = 0; h4 < 32; h4++) {
        float4 lv4 = Lrow4[h4];
        float lvs[4] = {lv4.x, lv4.y, lv4.z, lv4.w};
        #pragma unroll
        for (int hh = 0; hh < 4; hh++) {
            int h = h4 * 4 + hh;
            float lv = lvs[hh];
            float4 t = Tbase[h * 32];
            float2 lv2 = make_float2(lv, lv);
            float2 x01 = fadd2(lv2, make_float2(t.x, t.y));
            float2 x23 = fadd2(lv2, make_float2(t.z, t.w));
            float2 mx01 = make_float2(fmaxf(x01.x, 0.f), fmaxf(x01.y, 0.f));
            float2 mx23 = make_float2(fmaxf(x23.x, 0.f), fmaxf(x23.y, 0.f));
            float2 e01 = make_float2(__expf(fminf(x01.x, 0.f)), __expf(fminf(x01.y, 0.f)));
            float2 e23 = make_float2(__expf(fminf(x23.x, 0.f)), __expf(fminf(x23.y, 0.f)));
            float2 p01 = fadd2(fadd2(mx01, e01), neg1);
            float2 p23 = fadd2(fadd2(mx23, e23), neg1);
            float2 pd[4] = { make_float2(p01.x, p01.x), make_float2(p01.y, p01.y),
                             make_float2(p23.x, p23.x), make_float2(p23.y, p23.y) };
            const float4* wrow = Wbase + h * 8;
            float4 wv4[4];
            #pragma unroll
            for (int i = 0; i < 4; i++) wv4[i] = wrow[i];
            const float2* wk = (const float2*)wv4;   // 8 k-pairs
            #pragma unroll
            for (int p = 0; p < 4; p++)
                #pragma unroll
                for (int k = 0; k < 8; k++)
                    a[p][k] = ffma2(pd[p], wk[k], a[p][k]);
        }
    }

    int pair0 = (li_base + il) * 512 + jg * 128 + jq * 4;

    if (kh == 0) {
        // kp 0..4 -> pi[0..9]; kp 5..7 -> sg[0..5]
        float pib[10], sgb6[6];
        #pragma unroll
        for (int k = 0; k < 10; k++) pib[k] = __ldg(pi_b + k);
        #pragma unroll
        for (int k = 0; k < 6; k++) sgb6[k] = __ldg(sg_b + k);

        float obuf[40];
        #pragma unroll
        for (int jj = 0; jj < 4; jj++) {
            float v[10];
            #pragma unroll
            for (int k = 0; k < 10; k++) {
                float2 ak = a[jj][k >> 1];
                v[k] = ((k & 1) ? ak.y : ak.x) + pib[k];
            }
            float mx = v[0];
            #pragma unroll
            for (int k = 1; k < 10; k++) mx = fmaxf(mx, v[k]);
            float s = 0.f;
            #pragma unroll
            for (int k = 0; k < 10; k++) { v[k] = __expf(v[k] - mx); s += v[k]; }
            float inv = 1.0f / s;
            #pragma unroll
            for (int k = 0; k < 10; k++) obuf[jj * 10 + k] = v[k] * inv;
        }
        {
            float4* dst = (float4*)(out + OUT_PI + (size_t)pair0 * 10);
            #pragma unroll
            for (int q = 0; q < 10; q++) dst[q] = ((float4*)obuf)[q];
        }
        // sg[0..5]
        #pragma unroll
        for (int jj = 0; jj < 4; jj++) {
            float s6[6];
            #pragma unroll
            for (int si = 0; si < 6; si++) {
                float2 ak = a[jj][5 + (si >> 1)];
                float x = (si & 1) ? ak.y : ak.x;
                s6[si] = eluf(x + sgb6[si]) + 1.1f;
            }
            float* dst = out + OUT_SG + (size_t)(pair0 + jj) * 10;
            *(float2*)(dst + 0) = make_float2(s6[0], s6[1]);
            *(float2*)(dst + 2) = make_float2(s6[2], s6[3]);
            *(float2*)(dst + 4) = make_float2(s6[4], s6[5]);
        }
    } else {
        // kp 0..1 -> sg[6..9]; kp 2..6 -> mu[0..9]; kp 7 pad
        float sgb4[4], mub[10];
        #pragma unroll
        for (int k = 0; k < 4; k++) sgb4[k] = __ldg(sg_b + 6 + k);
        #pragma unroll
        for (int k = 0; k < 10; k++) mub[k] = __ldg(mu_b + k);

        #pragma unroll
        for (int jj = 0; jj < 4; jj++) {
            float s4[4];
            #pragma unroll
            for (int si = 0; si < 4; si++) {
                float2 ak = a[jj][si >> 1];
                float x = (si & 1) ? ak.y : ak.x;
                s4[si] = eluf(x + sgb4[si]) + 1.1f;
            }
            float* dst = out + OUT_SG + (size_t)(pair0 + jj) * 10;
            *(float2*)(dst + 6) = make_float2(s4[0], s4[1]);
            *(float2*)(dst + 8) = make_float2(s4[2], s4[3]);
        }
        float obuf[40];
        #pragma unroll
        for (int jj = 0; jj < 4; jj++)
            #pragma unroll
            for (int mi = 0; mi < 10; mi++) {
                float2 ak = a[jj][2 + (mi >> 1)];
                float x = (mi & 1) ? ak.y : ak.x;
                obuf[jj * 10 + mi] = eluf(x + mub[mi]) + 1.0f;
            }
        {
            float4* dst = (float4*)(out + OUT_MU + (size_t)pair0 * 10);
            #pragma unroll
            for (int q = 0; q < 10; q++) dst[q] = ((float4*)obuf)[q];
        }
    }
}

// ================================================================ launch
extern "C" void kernel_launch(void* const* d_in, const int* in_sizes, int n_in,
                              void* d_out, int out_size) {
    const float* lig_s  = (const float*)d_in[0];
    const float* pro_s  = (const float*)d_in[1];
    const int*   donar  = (const int*)d_in[4];
    const int*   eidx   = (const int*)d_in[5];
    const float* mlp_w  = (const float*)d_in[6];
    const float* mlp_b  = (const float*)d_in[7];
    const float* mlp_g  = (const float*)d_in[8];
    const float* mlp_be = (const float*)d_in[9];
    const float* mlp_m  = (const float*)d_in[10];
    const float* mlp_v  = (const float*)d_in[11];
    const float* sel_w1 = (const float*)d_in[12];
    const float* sel_b1 = (const float*)d_in[13];
    const float* sel_g  = (const float*)d_in[14];
    const float* sel_be = (const float*)d_in[15];
    const float* sel_m  = (const float*)d_in[16];
    const float* sel_v  = (const float*)d_in[17];
    const float* sel_w2 = (const float*)d_in[18];
    const float* sel_b2 = (const float*)d_in[19];
    const float* pi_w   = (const float*)d_in[20];
    const float* pi_b   = (const float*)d_in[21];
    const float* sg_w   = (const float*)d_in[22];
    const float* sg_b   = (const float*)d_in[23];
    const float* mu_w   = (const float*)d_in[24];
    const float* mu_b   = (const float*)d_in[25];
    const float* at_w   = (const float*)d_in[26];
    const float* at_b   = (const float*)d_in[27];
    const float* bt_w   = (const float*)d_in[28];
    const float* bt_b   = (const float*)d_in[29];
    float* out = (float*)d_out;

    float *Lh, *ThT, *Ls, *Ts;
    cudaGetSymbolAddress((void**)&Lh,  g_Lh);
    cudaGetSymbolAddress((void**)&ThT, g_ThT);
    cudaGetSymbolAddress((void**)&Ls,  g_Ls);
    cudaGetSymbolAddress((void**)&Ts,  g_Ts);

    cudaFuncSetAttribute((const void*)back_kernel,
                         cudaFuncAttributeMaxDynamicSharedMemorySize, SMEM_MAIN);

    front_kernel<<<FRONT_BLOCKS, 256>>>(
        lig_s, pro_s, eidx,
        mlp_w, mlp_b, mlp_g, mlp_be, mlp_m, mlp_v,
        sel_w1, sel_b1, sel_g, sel_be, sel_m, sel_v,
        at_w, at_b, bt_w, bt_b,
        Lh, ThT, Ls, Ts, out);

    back_kernel<<<BACK_BLOCKS, 512, SMEM_MAIN>>>(
        Lh, ThT, Ls, Ts,
        pi_w, pi_b, sg_w, sg_b, mu_w, mu_b,
        donar, sel_w2, sel_b2, out);
}

// round 15
// speedup vs baseline: 1.1932x; 1.0175x over previous
#include <cuda_runtime.h>
#include <cstdint>
#include <cstddef>

// ---------------------------------------------------------------- constants
#define B_   8
#define NL_  64
#define NT_  512
#define H_   128
#define E_   2048
#define M_   4096
#define P_TOT (B_*NL_*NT_)          // 262144 pairs

// output layout: tuple flattened in return order, float32
#define OUT_PI 0
#define OUT_SG (P_TOT*10)
#define OUT_MU (P_TOT*20)
#define OUT_CB (P_TOT*30)
#define OUT_AT (OUT_CB + P_TOT)
#define OUT_BT (OUT_AT + 512*18)
#define OUT_CD (OUT_BT + E_*5)
#define OUT_CM (OUT_CD + M_)

// ---------------------------------------------------------------- scratch
__device__ float g_Lh[512*128];     // lig @ W_top, BN folded
__device__ float g_ThT[128*4096];   // (pro @ W_bot)*s, TRANSPOSED [h][ti]
__device__ float g_Ls[512*128];     // selector lig part
__device__ float g_Ts[4096*128];    // selector pro part

// ---------------------------------------------------------------- helpers
__device__ __forceinline__ float eluf(float x) {
    return fmaxf(x, 0.f) + __expf(fminf(x, 0.f)) - 1.f;
}
__device__ __forceinline__ float2 ffma2(float2 a, float2 b, float2 c) {
    float2 d;
    asm("fma.rn.f32x2 %0, %1, %2, %3;"
        : "=l"(reinterpret_cast<unsigned long long&>(d))
        : "l"(reinterpret_cast<unsigned long long&>(a)),
          "l"(reinterpret_cast<unsigned long long&>(b)),
          "l"(reinterpret_cast<unsigned long long&>(c)));
    return d;
}
__device__ __forceinline__ float2 fadd2(float2 a, float2 b) {
    float2 d;
    asm("add.rn.f32x2 %0, %1, %2;"
        : "=l"(reinterpret_cast<unsigned long long&>(d))
        : "l"(reinterpret_cast<unsigned long long&>(a)),
          "l"(reinterpret_cast<unsigned long long&>(b)));
    return d;
}

// ================================================================ FRONT kernel
#define FRONT_BLOCKS 352

__device__ __forceinline__ void gemm64(
    const float* __restrict__ A, const float* __restrict__ W, int ldw, int wrow0, int N,
    int r0, int c0, int mode,
    const float* __restrict__ g, const float* __restrict__ be,
    const float* __restrict__ m, const float* __restrict__ v,
    const float* __restrict__ lb,
    float* __restrict__ C, int ldc, int transC,
    float (*Ast)[68], float (*Ws)[68]) {

    int tid = threadIdx.x;
    int tx = tid & 15, ty = tid >> 4;
    float2 acc2[4][2] = {};

    for (int kc = 0; kc < 128; kc += 64) {
        #pragma unroll
        for (int q = tid; q < 64 * 16; q += 256) {
            int r = q >> 4, k4 = q & 15;
            float4 val = *(const float4*)(A + (size_t)(r0 + r) * 128 + kc + k4 * 4);
            Ast[k4 * 4 + 0][r] = val.x;
            Ast[k4 * 4 + 1][r] = val.y;
            Ast[k4 * 4 + 2][r] = val.z;
            Ast[k4 * 4 + 3][r] = val.w;
        }
        #pragma unroll
        for (int q = tid; q < 64 * 64; q += 256) {
            int k = q >> 6, c = q & 63;
            float w = 0.f;
            if (c0 + c < N) w = W[(size_t)(wrow0 + kc + k) * ldw + c0 + c];
            Ws[k][c] = w;
        }
        __syncthreads();
        #pragma unroll 16
        for (int k = 0; k < 64; k++) {
            float4 a4 = *(const float4*)&Ast[k][ty * 4];
            float4 w4 = *(const float4*)&Ws[k][tx * 4];
            float2 wlo = make_float2(w4.x, w4.y);
            float2 whi = make_float2(w4.z, w4.w);
            float av[4] = {a4.x, a4.y, a4.z, a4.w};
            #pragma unroll
            for (int d = 0; d < 4; d++) {
                float2 ad = make_float2(av[d], av[d]);
                acc2[d][0] = ffma2(ad, wlo, acc2[d][0]);
                acc2[d][1] = ffma2(ad, whi, acc2[d][1]);
            }
        }
        __syncthreads();
    }

    if (transC) {
        // N==128 on this path. Stage scaled result transposed into smem
        // (flat stride 65 -> low bank conflicts), then store coalesced
        // float4 rows of ThT (block covers 64 consecutive ti columns).
        float* S = &Ast[0][0];   // 64*65 = 4160 <= 64*68 floats available
        #pragma unroll
        for (int e = 0; e < 4; e++) {
            int c = c0 + tx * 4 + e;
            float s = 1.f;
            if (mode == 0 || mode == 1) s = g[c] * rsqrtf(v[c] + 1e-5f);
            float cb = 0.f;
            if (mode == 0) cb = (lb[c] - m[c]) * s + be[c];
            #pragma unroll
            for (int d = 0; d < 4; d++) {
                float a = (e & 1) ? acc2[d][e >> 1].y : acc2[d][e >> 1].x;
                S[(tx * 4 + e) * 65 + ty * 4 + d] = a * s + cb;
            }
        }
        __syncthreads();
        #pragma unroll
        for (int q = tid; q < 64 * 16; q += 256) {
            int cl = q >> 4;          // local column (= ThT row offset)
            int r4 = q & 15;          // float4 index within the 64 rows
            const float* Sr = S + cl * 65 + r4 * 4;
            float4 val = make_float4(Sr[0], Sr[1], Sr[2], Sr[3]);
            *(float4*)(C + (size_t)(c0 + cl) * ldc + r0 + r4 * 4) = val;
        }
        __syncthreads();
        return;
    }

    #pragma unroll
    for (int e = 0; e < 4; e++) {
        int c = c0 + tx * 4 + e;
        if (c >= N) continue;
        float s = 1.f, cb = 0.f;
        if (mode == 0) {
            s = g[c] * rsqrtf(v[c] + 1e-5f);
            cb = (lb[c] - m[c]) * s + be[c];
        } else if (mode == 1) {
            s = g[c] * rsqrtf(v[c] + 1e-5f);
        } else {
            cb = lb[c];
        }
        #pragma unroll
        for (int d = 0; d < 4; d++) {
            int r = r0 + ty * 4 + d;
            float a = (e & 1) ? acc2[d][e >> 1].y : acc2[d][e >> 1].x;
            C[(size_t)r * ldc + c] = a * s + cb;
        }
    }
}

__global__ void __launch_bounds__(256)
front_kernel(const float* __restrict__ lig_s, const float* __restrict__ pro_s,
             const int* __restrict__ eidx,
             const float* __restrict__ mlp_w, const float* __restrict__ mlp_b,
             const float* __restrict__ mlp_g, const float* __restrict__ mlp_be,
             const float* __restrict__ mlp_m, const float* __restrict__ mlp_v,
             const float* __restrict__ sel_w1, const float* __restrict__ sel_b1,
             const float* __restrict__ sel_g, const float* __restrict__ sel_be,
             const float* __restrict__ sel_m, const float* __restrict__ sel_v,
             const float* __restrict__ at_w, const float* __restrict__ at_b,
             const float* __restrict__ bt_w, const float* __restrict__ bt_b,
             float* __restrict__ Lh, float* __restrict__ ThT,
             float* __restrict__ Ls, float* __restrict__ Ts,
             float* __restrict__ out) {
    __shared__ float Ast[64][68];
    __shared__ float Ws[64][68];
    int blk = blockIdx.x;
    int tid = threadIdx.x;

    if (blk < 16) {
        int i = blk;
        gemm64(lig_s, mlp_w, 128, 0, 128, (i >> 1) * 64, (i & 1) * 64, 0,
               mlp_g, mlp_be, mlp_m, mlp_v, mlp_b, Lh, 128, 0, Ast, Ws);
    } else if (blk < 32) {
        int i = blk - 16;
        gemm64(lig_s, sel_w1, 128, 0, 128, (i >> 1) * 64, (i & 1) * 64, 0,
               sel_g, sel_be, sel_m, sel_v, sel_b1, Ls, 128, 0, Ast, Ws);
    } else if (blk < 40) {
        int i = blk - 32;
        gemm64(lig_s, at_w, 18, 0, 18, i * 64, 0, 2,
               nullptr, nullptr, nullptr, nullptr, at_b, out + OUT_AT, 18, 0, Ast, Ws);
    } else if (blk < 168) {
        int i = blk - 40;
        gemm64(pro_s, mlp_w, 128, 128, 128, (i >> 1) * 64, (i & 1) * 64, 1,
               mlp_g, nullptr, nullptr, mlp_v, nullptr, ThT, 4096, 1, Ast, Ws);
    } else if (blk < 296) {
        int i = blk - 168;
        gemm64(pro_s, sel_w1, 128, 128, 128, (i >> 1) * 64, (i & 1) * 64, 1,
               sel_g, nullptr, nullptr, sel_v, nullptr, Ts, 128, 0, Ast, Ws);
    } else if (blk < 336) {
        int t = (blk - 296) * 256 + tid;
        if (t < E_ * 5) {
            int e = t / 5, c = t - e * 5;
            int e0 = eidx[e], e1 = eidx[E_ + e];
            float acc = bt_b[c];
            const float* r0 = lig_s + (size_t)e0 * 128;
            const float* r1 = lig_s + (size_t)e1 * 128;
            #pragma unroll 4
            for (int k = 0; k < 128; k++) acc = fmaf(r0[k], __ldg(bt_w + k * 5 + c), acc);
            #pragma unroll 4
            for (int k = 0; k < 128; k++) acc = fmaf(r1[k], __ldg(bt_w + (128 + k) * 5 + c), acc);
            out[OUT_BT + t] = acc;
        }
    } else {
        int base = (blk - 336) * 4096;
        float4* cb = (float4*)(out + OUT_CB);
        float4* cm = (float4*)(out + OUT_CM);
        const float4 ones = make_float4(1.f, 1.f, 1.f, 1.f);
        #pragma unroll
        for (int it = 0; it < 16; it++) {
            int q = base + it * 256 + tid;
            float b = (float)((q * 4) >> 15);
            cb[q] = make_float4(b, b, b, b);
            cm[q] = ones;
        }
    }
}

// ================================================================ BACK kernel
// blocks [0,256): pairwise MDN head. Tile 8 lig x 128 pro, 512 threads.
//   thread = (il 0..7, jq 0..31, kh 0..1): 4 pairs x 8 k-PAIRS
//   k-packed FFMA2: acc{k,k+1} += {p,p} * {w_k, w_k+1}   (no weight duplication)
//   kh0 -> heads k 0..15 (pi[0..9], sg[0..5]); kh1 -> k 16..31 (sg[6..9], mu[0..9], pad)
// blocks [256,272): donor selector
// smem: Th 64KB + L 4KB + Wk 16KB = 84KB
#define SMEM_MAIN (128*128*4 + 8*128*4 + 128*16*8)
#define BACK_BLOCKS 272

__global__ void __launch_bounds__(512, 1)
back_kernel(const float* __restrict__ Lh, const float* __restrict__ ThT,
            const float* __restrict__ Ls, const float* __restrict__ Ts,
            const float* __restrict__ pi_w, const float* __restrict__ pi_b,
            const float* __restrict__ sg_w, const float* __restrict__ sg_b,
            const float* __restrict__ mu_w, const float* __restrict__ mu_b,
            const int* __restrict__ donar_idx,
            const float* __restrict__ sel_w2, const float* __restrict__ sel_b2,
            float* __restrict__ out) {
    int tid = threadIdx.x;
    int blk = blockIdx.x;

    if (blk >= 256) {
        // ---------------- donor selector ----------------
        int w = tid >> 5, lane = tid & 31;
        float w2v[4];
        #pragma unroll
        for (int hq = 0; hq < 4; hq++) w2v[hq] = __ldg(sel_w2 + lane + hq * 32);
        float b2 = __ldg(sel_b2);
        #pragma unroll 2
        for (int it = 0; it < 16; it++) {
            int mm = (blk - 256) * 256 + it * 16 + w;
            int p = donar_idx[mm];
            int li = p / 512;
            int ti = (p >> 15) * 512 + (p & 511);
            float acc = 0.f;
            #pragma unroll
            for (int hq = 0; hq < 4; hq++) {
                int h = lane + hq * 32;
                float x = Ls[(size_t)li * 128 + h] + Ts[(size_t)ti * 128 + h];
                acc = fmaf(eluf(x), w2v[hq], acc);
            }
            #pragma unroll
            for (int o = 16; o; o >>= 1) acc += __shfl_xor_sync(0xffffffffu, acc, o);
            if (lane == 0) out[OUT_CD + mm] = 1.f / (1.f + __expf(-(acc + b2)));
        }
        return;
    }

    // ---------------- pairwise MDN ----------------
    extern __shared__ float sm[];
    float*  Th_s = sm;                           // [h][j] stride 128 (64KB)
    float*  L_s  = sm + 128 * 128;               // [il][h] (4KB)
    float2* Wk   = (float2*)(L_s + 8 * 128);     // [h][kp 0..15] = {w[2kp],w[2kp+1]} (16KB)

    int jg = blk & 3;
    int ig = (blk >> 2) & 7;
    int b  = blk >> 5;
    int ti_base = b * 512 + jg * 128;
    int li_base = b * 64 + ig * 8;

    #pragma unroll
    for (int q = tid; q < 128 * 32; q += 512) {
        int h = q >> 5, j4 = q & 31;
        float4 v = *(const float4*)(ThT + (size_t)h * 4096 + ti_base + j4 * 4);
        *(float4*)&Th_s[h * 128 + j4 * 4] = v;
    }
    if (tid < 8 * 32) {
        int r = tid >> 5, k4 = tid & 31;
        *(float4*)&L_s[r * 128 + k4 * 4] =
            *(const float4*)(Lh + (size_t)(li_base + r) * 128 + k4 * 4);
    }
    // weights, k-pair packed, NOT duplicated: Wk[h*16+kp] = {w[2kp], w[2kp+1]}, k>=30 -> 0
    #pragma unroll
    for (int q = tid; q < 128 * 16; q += 512) {
        int h  = q >> 4;
        int kp = q & 15;
        float wv[2];
        #pragma unroll
        for (int c = 0; c < 2; c++) {
            int k = 2 * kp + c;
            wv[c] = (k < 10) ? pi_w[h * 10 + k]
                  : (k < 20) ? sg_w[h * 10 + k - 10]
                  : (k < 30) ? mu_w[h * 10 + k - 20]
                             : 0.f;
        }
        Wk[q] = make_float2(wv[0], wv[1]);
    }
    __syncthreads();

    int il = tid >> 6;
    int r6 = tid & 63;
    int jq = r6 >> 1;          // 0..31, pairs j = jq*4 .. +3
    int kh = r6 & 1;           // k half: kp 0..7 or 8..15

    const float4* Lrow4 = (const float4*)(L_s + il * 128);
    const float4* Tbase = (const float4*)Th_s + jq;            // + h*32
    const float4* Wbase = (const float4*)Wk + kh * 4;          // + h*8, 4 float4 = 8 float2

    float2 a[4][8];            // [pair][kp]
    #pragma unroll
    for (int p = 0; p < 4; p++)
        #pragma unroll
        for (int k = 0; k < 8; k++) a[p][k] = make_float2(0.f, 0.f);

    const float2 neg1 = make_float2(-1.f, -1.f);

    #pragma unroll 2
    for (int h4 = 0; h4 < 32; h4++) {
        float4 lv4 = Lrow4[h4];
        float lvs[4] = {lv4.x, lv4.y, lv4.z, lv4.w};
        #pragma unroll
        for (int hh = 0; hh < 4; hh++) {
            int h = h4 * 4 + hh;
            float lv = lvs[hh];
            float4 t = Tbase[h * 32];
            float2 lv2 = make_float2(lv, lv);
            float2 x01 = fadd2(lv2, make_float2(t.x, t.y));
            float2 x23 = fadd2(lv2, make_float2(t.z, t.w));
            float2 mx01 = make_float2(fmaxf(x01.x, 0.f), fmaxf(x01.y, 0.f));
            float2 mx23 = make_float2(fmaxf(x23.x, 0.f), fmaxf(x23.y, 0.f));
            float2 e01 = make_float2(__expf(fminf(x01.x, 0.f)), __expf(fminf(x01.y, 0.f)));
            float2 e23 = make_float2(__expf(fminf(x23.x, 0.f)), __expf(fminf(x23.y, 0.f)));
            float2 p01 = fadd2(fadd2(mx01, e01), neg1);
            float2 p23 = fadd2(fadd2(mx23, e23), neg1);
            float2 pd[4] = { make_float2(p01.x, p01.x), make_float2(p01.y, p01.y),
                             make_float2(p23.x, p23.x), make_float2(p23.y, p23.y) };
            const float4* wrow = Wbase + h * 8;
            float4 wv4[4];
            #pragma unroll
            for (int i = 0; i < 4; i++) wv4[i] = wrow[i];
            const float2* wk = (const float2*)wv4;   // 8 k-pairs
            #pragma unroll
            for (int p = 0; p < 4; p++)
                #pragma unroll
                for (int k = 0; k < 8; k++)
                    a[p][k] = ffma2(pd[p], wk[k], a[p][k]);
        }
    }

    int pair0 = (li_base + il) * 512 + jg * 128 + jq * 4;

    if (kh == 0) {
        // kp 0..4 -> pi[0..9]; kp 5..7 -> sg[0..5]
        float pib[10], sgb6[6];
        #pragma unroll
        for (int k = 0; k < 10; k++) pib[k] = __ldg(pi_b + k);
        #pragma unroll
        for (int k = 0; k < 6; k++) sgb6[k] = __ldg(sg_b + k);

        float obuf[40];
        #pragma unroll
        for (int jj = 0; jj < 4; jj++) {
            float v[10];
            #pragma unroll
            for (int k = 0; k < 10; k++) {
                float2 ak = a[jj][k >> 1];
                v[k] = ((k & 1) ? ak.y : ak.x) + pib[k];
            }
            float mx = v[0];
            #pragma unroll
            for (int k = 1; k < 10; k++) mx = fmaxf(mx, v[k]);
            float s = 0.f;
            #pragma unroll
            for (int k = 0; k < 10; k++) { v[k] = __expf(v[k] - mx); s += v[k]; }
            float inv = 1.0f / s;
            #pragma unroll
            for (int k = 0; k < 10; k++) obuf[jj * 10 + k] = v[k] * inv;
        }
        {
            float4* dst = (float4*)(out + OUT_PI + (size_t)pair0 * 10);
            #pragma unroll
            for (int q = 0; q < 10; q++) dst[q] = ((float4*)obuf)[q];
        }
        // sg[0..5]
        #pragma unroll
        for (int jj = 0; jj < 4; jj++) {
            float s6[6];
            #pragma unroll
            for (int si = 0; si < 6; si++) {
                float2 ak = a[jj][5 + (si >> 1)];
                float x = (si & 1) ? ak.y : ak.x;
                s6[si] = eluf(x + sgb6[si]) + 1.1f;
            }
            float* dst = out + OUT_SG + (size_t)(pair0 + jj) * 10;
            *(float2*)(dst + 0) = make_float2(s6[0], s6[1]);
            *(float2*)(dst + 2) = make_float2(s6[2], s6[3]);
            *(float2*)(dst + 4) = make_float2(s6[4], s6[5]);
        }
    } else {
        // kp 0..1 -> sg[6..9]; kp 2..6 -> mu[0..9]; kp 7 pad
        float sgb4[4], mub[10];
        #pragma unroll
        for (int k = 0; k < 4; k++) sgb4[k] = __ldg(sg_b + 6 + k);
        #pragma unroll
        for (int k = 0; k < 10; k++) mub[k] = __ldg(mu_b + k);

        #pragma unroll
        for (int jj = 0; jj < 4; jj++) {
            float s4[4];
            #pragma unroll
            for (int si = 0; si < 4; si++) {
                float2 ak = a[jj][si >> 1];
                float x = (si & 1) ? ak.y : ak.x;
                s4[si] = eluf(x + sgb4[si]) + 1.1f;
            }
            float* dst = out + OUT_SG + (size_t)(pair0 + jj) * 10;
            *(float2*)(dst + 6) = make_float2(s4[0], s4[1]);
            *(float2*)(dst + 8) = make_float2(s4[2], s4[3]);
        }
        float obuf[40];
        #pragma unroll
        for (int jj = 0; jj < 4; jj++)
            #pragma unroll
            for (int mi = 0; mi < 10; mi++) {
                float2 ak = a[jj][2 + (mi >> 1)];
                float x = (mi & 1) ? ak.y : ak.x;
                obuf[jj * 10 + mi] = eluf(x + mub[mi]) + 1.0f;
            }
        {
            float4* dst = (float4*)(out + OUT_MU + (size_t)pair0 * 10);
            #pragma unroll
            for (int q = 0; q < 10; q++) dst[q] = ((float4*)obuf)[q];
        }
    }
}

// ================================================================ launch
extern "C" void kernel_launch(void* const* d_in, const int* in_sizes, int n_in,
                              void* d_out, int out_size) {
    const float* lig_s  = (const float*)d_in[0];
    const float* pro_s  = (const float*)d_in[1];
    const int*   donar  = (const int*)d_in[4];
    const int*   eidx   = (const int*)d_in[5];
    const float* mlp_w  = (const float*)d_in[6];
    const float* mlp_b  = (const float*)d_in[7];
    const float* mlp_g  = (const float*)d_in[8];
    const float* mlp_be = (const float*)d_in[9];
    const float* mlp_m  = (const float*)d_in[10];
    const float* mlp_v  = (const float*)d_in[11];
    const float* sel_w1 = (const float*)d_in[12];
    const float* sel_b1 = (const float*)d_in[13];
    const float* sel_g  = (const float*)d_in[14];
    const float* sel_be = (const float*)d_in[15];
    const float* sel_m  = (const float*)d_in[16];
    const float* sel_v  = (const float*)d_in[17];
    const float* sel_w2 = (const float*)d_in[18];
    const float* sel_b2 = (const float*)d_in[19];
    const float* pi_w   = (const float*)d_in[20];
    const float* pi_b   = (const float*)d_in[21];
    const float* sg_w   = (const float*)d_in[22];
    const float* sg_b   = (const float*)d_in[23];
    const float* mu_w   = (const float*)d_in[24];
    const float* mu_b   = (const float*)d_in[25];
    const float* at_w   = (const float*)d_in[26];
    const float* at_b   = (const float*)d_in[27];
    const float* bt_w   = (const float*)d_in[28];
    const float* bt_b   = (const float*)d_in[29];
    float* out = (float*)d_out;

    float *Lh, *ThT, *Ls, *Ts;
    cudaGetSymbolAddress((void**)&Lh,  g_Lh);
    cudaGetSymbolAddress((void**)&ThT, g_ThT);
    cudaGetSymbolAddress((void**)&Ls,  g_Ls);
    cudaGetSymbolAddress((void**)&Ts,  g_Ts);

    cudaFuncSetAttribute((const void*)back_kernel,
                         cudaFuncAttributeMaxDynamicSharedMemorySize, SMEM_MAIN);

    front_kernel<<<FRONT_BLOCKS, 256>>>(
        lig_s, pro_s, eidx,
        mlp_w, mlp_b, mlp_g, mlp_be, mlp_m, mlp_v,
        sel_w1, sel_b1, sel_g, sel_be, sel_m, sel_v,
        at_w, at_b, bt_w, bt_b,
        Lh, ThT, Ls, Ts, out);

    back_kernel<<<BACK_BLOCKS, 512, SMEM_MAIN>>>(
        Lh, ThT, Ls, Ts,
        pi_w, pi_b, sg_w, sg_b, mu_w, mu_b,
        donar, sel_w2, sel_b2, out);
}

// round 16
// speedup vs baseline: 1.2517x; 1.0490x over previous
#include <cuda_runtime.h>
#include <cstdint>
#include <cstddef>

// ---------------------------------------------------------------- constants
#define B_   8
#define NL_  64
#define NT_  512
#define H_   128
#define E_   2048
#define M_   4096
#define P_TOT (B_*NL_*NT_)          // 262144 pairs

// output layout: tuple flattened in return order, float32
#define OUT_PI 0
#define OUT_SG (P_TOT*10)
#define OUT_MU (P_TOT*20)
#define OUT_CB (P_TOT*30)
#define OUT_AT (OUT_CB + P_TOT)
#define OUT_BT (OUT_AT + 512*18)
#define OUT_CD (OUT_BT + E_*5)
#define OUT_CM (OUT_CD + M_)

// ---------------------------------------------------------------- scratch
__device__ float g_Lh[512*128];     // lig @ W_top, BN folded
__device__ float g_ThT[128*4096];   // (pro @ W_bot)*s, TRANSPOSED [h][ti]
__device__ float g_Ls[512*128];     // selector lig part
__device__ float g_Ts[4096*128];    // selector pro part

// ---------------------------------------------------------------- helpers
__device__ __forceinline__ float eluf(float x) {
    return fmaxf(x, 0.f) + __expf(fminf(x, 0.f)) - 1.f;
}
__device__ __forceinline__ float2 ffma2(float2 a, float2 b, float2 c) {
    float2 d;
    asm("fma.rn.f32x2 %0, %1, %2, %3;"
        : "=l"(reinterpret_cast<unsigned long long&>(d))
        : "l"(reinterpret_cast<unsigned long long&>(a)),
          "l"(reinterpret_cast<unsigned long long&>(b)),
          "l"(reinterpret_cast<unsigned long long&>(c)));
    return d;
}
__device__ __forceinline__ float2 fadd2(float2 a, float2 b) {
    float2 d;
    asm("add.rn.f32x2 %0, %1, %2;"
        : "=l"(reinterpret_cast<unsigned long long&>(d))
        : "l"(reinterpret_cast<unsigned long long&>(a)),
          "l"(reinterpret_cast<unsigned long long&>(b)));
    return d;
}

// ================================================================ FRONT kernel
#define FRONT_BLOCKS 352

__device__ __forceinline__ void gemm64(
    const float* __restrict__ A, const float* __restrict__ W, int ldw, int wrow0, int N,
    int r0, int c0, int mode,
    const float* __restrict__ g, const float* __restrict__ be,
    const float* __restrict__ m, const float* __restrict__ v,
    const float* __restrict__ lb,
    float* __restrict__ C, int ldc, int transC,
    float (*Ast)[68], float (*Ws)[68]) {

    int tid = threadIdx.x;
    int tx = tid & 15, ty = tid >> 4;
    float2 acc2[4][2] = {};

    for (int kc = 0; kc < 128; kc += 64) {
        #pragma unroll
        for (int q = tid; q < 64 * 16; q += 256) {
            int r = q >> 4, k4 = q & 15;
            float4 val = *(const float4*)(A + (size_t)(r0 + r) * 128 + kc + k4 * 4);
            Ast[k4 * 4 + 0][r] = val.x;
            Ast[k4 * 4 + 1][r] = val.y;
            Ast[k4 * 4 + 2][r] = val.z;
            Ast[k4 * 4 + 3][r] = val.w;
        }
        #pragma unroll
        for (int q = tid; q < 64 * 64; q += 256) {
            int k = q >> 6, c = q & 63;
            float w = 0.f;
            if (c0 + c < N) w = W[(size_t)(wrow0 + kc + k) * ldw + c0 + c];
            Ws[k][c] = w;
        }
        __syncthreads();
        #pragma unroll 16
        for (int k = 0; k < 64; k++) {
            float4 a4 = *(const float4*)&Ast[k][ty * 4];
            float4 w4 = *(const float4*)&Ws[k][tx * 4];
            float2 wlo = make_float2(w4.x, w4.y);
            float2 whi = make_float2(w4.z, w4.w);
            float av[4] = {a4.x, a4.y, a4.z, a4.w};
            #pragma unroll
            for (int d = 0; d < 4; d++) {
                float2 ad = make_float2(av[d], av[d]);
                acc2[d][0] = ffma2(ad, wlo, acc2[d][0]);
                acc2[d][1] = ffma2(ad, whi, acc2[d][1]);
            }
        }
        __syncthreads();
    }

    if (transC) {
        // N==128 on this path. Stage scaled result transposed into smem,
        // then store coalesced float4 rows of ThT.
        float* S = &Ast[0][0];   // 64*65 = 4160 <= 64*68 floats available
        #pragma unroll
        for (int e = 0; e < 4; e++) {
            int c = c0 + tx * 4 + e;
            float s = 1.f;
            if (mode == 0 || mode == 1) s = g[c] * rsqrtf(v[c] + 1e-5f);
            float cb = 0.f;
            if (mode == 0) cb = (lb[c] - m[c]) * s + be[c];
            #pragma unroll
            for (int d = 0; d < 4; d++) {
                float a = (e & 1) ? acc2[d][e >> 1].y : acc2[d][e >> 1].x;
                S[(tx * 4 + e) * 65 + ty * 4 + d] = a * s + cb;
            }
        }
        __syncthreads();
        #pragma unroll
        for (int q = tid; q < 64 * 16; q += 256) {
            int cl = q >> 4;
            int r4 = q & 15;
            const float* Sr = S + cl * 65 + r4 * 4;
            float4 val = make_float4(Sr[0], Sr[1], Sr[2], Sr[3]);
            *(float4*)(C + (size_t)(c0 + cl) * ldc + r0 + r4 * 4) = val;
        }
        __syncthreads();
        return;
    }

    #pragma unroll
    for (int e = 0; e < 4; e++) {
        int c = c0 + tx * 4 + e;
        if (c >= N) continue;
        float s = 1.f, cb = 0.f;
        if (mode == 0) {
            s = g[c] * rsqrtf(v[c] + 1e-5f);
            cb = (lb[c] - m[c]) * s + be[c];
        } else if (mode == 1) {
            s = g[c] * rsqrtf(v[c] + 1e-5f);
        } else {
            cb = lb[c];
        }
        #pragma unroll
        for (int d = 0; d < 4; d++) {
            int r = r0 + ty * 4 + d;
            float a = (e & 1) ? acc2[d][e >> 1].y : acc2[d][e >> 1].x;
            C[(size_t)r * ldc + c] = a * s + cb;
        }
    }
}

__global__ void __launch_bounds__(256)
front_kernel(const float* __restrict__ lig_s, const float* __restrict__ pro_s,
             const int* __restrict__ eidx,
             const float* __restrict__ mlp_w, const float* __restrict__ mlp_b,
             const float* __restrict__ mlp_g, const float* __restrict__ mlp_be,
             const float* __restrict__ mlp_m, const float* __restrict__ mlp_v,
             const float* __restrict__ sel_w1, const float* __restrict__ sel_b1,
             const float* __restrict__ sel_g, const float* __restrict__ sel_be,
             const float* __restrict__ sel_m, const float* __restrict__ sel_v,
             const float* __restrict__ at_w, const float* __restrict__ at_b,
             const float* __restrict__ bt_w, const float* __restrict__ bt_b,
             float* __restrict__ Lh, float* __restrict__ ThT,
             float* __restrict__ Ls, float* __restrict__ Ts,
             float* __restrict__ out) {
    __shared__ float Ast[64][68];
    __shared__ float Ws[64][68];
    int blk = blockIdx.x;
    int tid = threadIdx.x;

    if (blk < 16) {
        int i = blk;
        gemm64(lig_s, mlp_w, 128, 0, 128, (i >> 1) * 64, (i & 1) * 64, 0,
               mlp_g, mlp_be, mlp_m, mlp_v, mlp_b, Lh, 128, 0, Ast, Ws);
    } else if (blk < 32) {
        int i = blk - 16;
        gemm64(lig_s, sel_w1, 128, 0, 128, (i >> 1) * 64, (i & 1) * 64, 0,
               sel_g, sel_be, sel_m, sel_v, sel_b1, Ls, 128, 0, Ast, Ws);
    } else if (blk < 40) {
        int i = blk - 32;
        gemm64(lig_s, at_w, 18, 0, 18, i * 64, 0, 2,
               nullptr, nullptr, nullptr, nullptr, at_b, out + OUT_AT, 18, 0, Ast, Ws);
    } else if (blk < 168) {
        int i = blk - 40;
        gemm64(pro_s, mlp_w, 128, 128, 128, (i >> 1) * 64, (i & 1) * 64, 1,
               mlp_g, nullptr, nullptr, mlp_v, nullptr, ThT, 4096, 1, Ast, Ws);
    } else if (blk < 296) {
        int i = blk - 168;
        gemm64(pro_s, sel_w1, 128, 128, 128, (i >> 1) * 64, (i & 1) * 64, 1,
               sel_g, nullptr, nullptr, sel_v, nullptr, Ts, 128, 0, Ast, Ws);
    } else if (blk < 336) {
        int t = (blk - 296) * 256 + tid;
        if (t < E_ * 5) {
            int e = t / 5, c = t - e * 5;
            int e0 = eidx[e], e1 = eidx[E_ + e];
            float acc = bt_b[c];
            const float* r0 = lig_s + (size_t)e0 * 128;
            const float* r1 = lig_s + (size_t)e1 * 128;
            #pragma unroll 4
            for (int k = 0; k < 128; k++) acc = fmaf(r0[k], __ldg(bt_w + k * 5 + c), acc);
            #pragma unroll 4
            for (int k = 0; k < 128; k++) acc = fmaf(r1[k], __ldg(bt_w + (128 + k) * 5 + c), acc);
            out[OUT_BT + t] = acc;
        }
    } else {
        int base = (blk - 336) * 4096;
        float4* cb = (float4*)(out + OUT_CB);
        float4* cm = (float4*)(out + OUT_CM);
        const float4 ones = make_float4(1.f, 1.f, 1.f, 1.f);
        #pragma unroll
        for (int it = 0; it < 16; it++) {
            int q = base + it * 256 + tid;
            float b = (float)((q * 4) >> 15);
            cb[q] = make_float4(b, b, b, b);
            cm[q] = ones;
        }
    }
}

// ================================================================ BACK kernel
// Higher-occupancy variant: 256 threads, 3 blocks/SM (24 warps = 6/SMSP).
// blocks [0,1024): pair tile 4 lig x 64 pro. thread = (il 0..3, jq 0..31, kh 0..1):
//   2 pairs (j = jq*2..+1) x 8 k-PAIRS (k-packed FFMA2, identical math to champion).
// blocks [1024,1040): donor selector (256 donors each).
// smem: Th 32KB | L 2KB | Wk 16KB = 50KB; 3 blocks/SM = 150KB
#define SMEM_MAIN (128*64*4 + 4*128*4 + 128*16*8)   // 51200
#define BACK_BLOCKS 1040

__global__ void __launch_bounds__(256, 3)
back_kernel(const float* __restrict__ Lh, const float* __restrict__ ThT,
            const float* __restrict__ Ls, const float* __restrict__ Ts,
            const float* __restrict__ pi_w, const float* __restrict__ pi_b,
            const float* __restrict__ sg_w, const float* __restrict__ sg_b,
            const float* __restrict__ mu_w, const float* __restrict__ mu_b,
            const int* __restrict__ donar_idx,
            const float* __restrict__ sel_w2, const float* __restrict__ sel_b2,
            float* __restrict__ out) {
    int tid = threadIdx.x;
    int blk = blockIdx.x;

    if (blk >= 1024) {
        // ---------------- donor selector: 16 blocks x 8 warps x 32 ----------------
        int w = tid >> 5, lane = tid & 31;
        float w2v[4];
        #pragma unroll
        for (int hq = 0; hq < 4; hq++) w2v[hq] = __ldg(sel_w2 + lane + hq * 32);
        float b2 = __ldg(sel_b2);
        #pragma unroll 2
        for (int it = 0; it < 32; it++) {
            int mm = (blk - 1024) * 256 + it * 8 + w;
            int p = donar_idx[mm];
            int li = p / 512;
            int ti = (p >> 15) * 512 + (p & 511);
            float acc = 0.f;
            #pragma unroll
            for (int hq = 0; hq < 4; hq++) {
                int h = lane + hq * 32;
                float x = Ls[(size_t)li * 128 + h] + Ts[(size_t)ti * 128 + h];
                acc = fmaf(eluf(x), w2v[hq], acc);
            }
            #pragma unroll
            for (int o = 16; o; o >>= 1) acc += __shfl_xor_sync(0xffffffffu, acc, o);
            if (lane == 0) out[OUT_CD + mm] = 1.f / (1.f + __expf(-(acc + b2)));
        }
        return;
    }

    // ---------------- pairwise MDN ----------------
    extern __shared__ float sm[];
    float*  Th_s = sm;                           // [h][j] stride 64 (32KB)
    float*  L_s  = sm + 128 * 64;                // [il][h] (2KB)
    float2* Wk   = (float2*)(L_s + 4 * 128);     // [h][kp 0..15] (16KB)

    int jh = blk & 7;            // 8 pro groups of 64
    int ig = (blk >> 3) & 15;    // 16 lig groups of 4
    int b  = blk >> 7;           // 0..7
    int ti_base = b * 512 + jh * 64;
    int li_base = b * 64 + ig * 4;

    // Th tile: 128 h x 16 float4
    #pragma unroll
    for (int q = tid; q < 128 * 16; q += 256) {
        int h = q >> 4, j4 = q & 15;
        float4 v = *(const float4*)(ThT + (size_t)h * 4096 + ti_base + j4 * 4);
        *(float4*)&Th_s[h * 64 + j4 * 4] = v;
    }
    if (tid < 4 * 32) {
        int r = tid >> 5, k4 = tid & 31;
        *(float4*)&L_s[r * 128 + k4 * 4] =
            *(const float4*)(Lh + (size_t)(li_base + r) * 128 + k4 * 4);
    }
    // weights, k-pair packed: Wk[h*16+kp] = {w[2kp], w[2kp+1]}, k>=30 -> 0
    #pragma unroll
    for (int q = tid; q < 128 * 16; q += 256) {
        int h  = q >> 4;
        int kp = q & 15;
        float wv[2];
        #pragma unroll
        for (int c = 0; c < 2; c++) {
            int k = 2 * kp + c;
            wv[c] = (k < 10) ? pi_w[h * 10 + k]
                  : (k < 20) ? sg_w[h * 10 + k - 10]
                  : (k < 30) ? mu_w[h * 10 + k - 20]
                             : 0.f;
        }
        Wk[q] = make_float2(wv[0], wv[1]);
    }
    __syncthreads();

    int il = tid >> 6;           // 0..3
    int r6 = tid & 63;
    int jq = r6 >> 1;            // 0..31, pairs j = jq*2, jq*2+1
    int kh = r6 & 1;             // k half: kp 0..7 or 8..15

    const float4* Lrow4 = (const float4*)(L_s + il * 128);
    const float2* T2    = (const float2*)Th_s + jq;            // + h*32
    const float4* Wbase = (const float4*)Wk + kh * 4;          // + h*8

    float2 a[2][8];              // [pair][kp]
    #pragma unroll
    for (int p = 0; p < 2; p++)
        #pragma unroll
        for (int k = 0; k < 8; k++) a[p][k] = make_float2(0.f, 0.f);

    const float2 neg1 = make_float2(-1.f, -1.f);

    #pragma unroll 2
    for (int h4 = 0; h4 < 32; h4++) {
        float4 lv4 = Lrow4[h4];
        float lvs[4] = {lv4.x, lv4.y, lv4.z, lv4.w};
        #pragma unroll
        for (int hh = 0; hh < 4; hh++) {
            int h = h4 * 4 + hh;
            float lv = lvs[hh];
            float2 t = T2[h * 32];
            float2 lv2 = make_float2(lv, lv);
            float2 x01 = fadd2(lv2, t);
            float2 mx01 = make_float2(fmaxf(x01.x, 0.f), fmaxf(x01.y, 0.f));
            float2 e01 = make_float2(__expf(fminf(x01.x, 0.f)), __expf(fminf(x01.y, 0.f)));
            float2 p01 = fadd2(fadd2(mx01, e01), neg1);
            float2 pd[2] = { make_float2(p01.x, p01.x), make_float2(p01.y, p01.y) };
            const float4* wrow = Wbase + h * 8;
            float4 wv4[4];
            #pragma unroll
            for (int i = 0; i < 4; i++) wv4[i] = wrow[i];
            const float2* wk = (const float2*)wv4;   // 8 k-pairs
            #pragma unroll
            for (int p = 0; p < 2; p++)
                #pragma unroll
                for (int k = 0; k < 8; k++)
                    a[p][k] = ffma2(pd[p], wk[k], a[p][k]);
        }
    }

    int pair0 = (li_base + il) * 512 + jh * 64 + jq * 2;

    if (kh == 0) {
        // kp 0..4 -> pi[0..9]; kp 5..7 -> sg[0..5]
        float pib[10], sgb6[6];
        #pragma unroll
        for (int k = 0; k < 10; k++) pib[k] = __ldg(pi_b + k);
        #pragma unroll
        for (int k = 0; k < 6; k++) sgb6[k] = __ldg(sg_b + k);

        #pragma unroll
        for (int jj = 0; jj < 2; jj++) {
            float v[10];
            #pragma unroll
            for (int k = 0; k < 10; k++) {
                float2 ak = a[jj][k >> 1];
                v[k] = ((k & 1) ? ak.y : ak.x) + pib[k];
            }
            float mx = v[0];
            #pragma unroll
            for (int k = 1; k < 10; k++) mx = fmaxf(mx, v[k]);
            float s = 0.f;
            #pragma unroll
            for (int k = 0; k < 10; k++) { v[k] = __expf(v[k] - mx); s += v[k]; }
            float inv = 1.0f / s;
            float2* dp = (float2*)(out + OUT_PI + (size_t)(pair0 + jj) * 10);
            #pragma unroll
            for (int k = 0; k < 5; k++) dp[k] = make_float2(v[2*k] * inv, v[2*k+1] * inv);

            float s6[6];
            #pragma unroll
            for (int si = 0; si < 6; si++) {
                float2 ak = a[jj][5 + (si >> 1)];
                float x = (si & 1) ? ak.y : ak.x;
                s6[si] = eluf(x + sgb6[si]) + 1.1f;
            }
            float* dst = out + OUT_SG + (size_t)(pair0 + jj) * 10;
            *(float2*)(dst + 0) = make_float2(s6[0], s6[1]);
            *(float2*)(dst + 2) = make_float2(s6[2], s6[3]);
            *(float2*)(dst + 4) = make_float2(s6[4], s6[5]);
        }
    } else {
        // kp 0..1 -> sg[6..9]; kp 2..6 -> mu[0..9]; kp 7 pad
        float sgb4[4], mub[10];
        #pragma unroll
        for (int k = 0; k < 4; k++) sgb4[k] = __ldg(sg_b + 6 + k);
        #pragma unroll
        for (int k = 0; k < 10; k++) mub[k] = __ldg(mu_b + k);

        #pragma unroll
        for (int jj = 0; jj < 2; jj++) {
            float s4[4];
            #pragma unroll
            for (int si = 0; si < 4; si++) {
                float2 ak = a[jj][si >> 1];
                float x = (si & 1) ? ak.y : ak.x;
                s4[si] = eluf(x + sgb4[si]) + 1.1f;
            }
            float* dst = out + OUT_SG + (size_t)(pair0 + jj) * 10;
            *(float2*)(dst + 6) = make_float2(s4[0], s4[1]);
            *(float2*)(dst + 8) = make_float2(s4[2], s4[3]);

            float mv[10];
            #pragma unroll
            for (int mi = 0; mi < 10; mi++) {
                float2 ak = a[jj][2 + (mi >> 1)];
                float x = (mi & 1) ? ak.y : ak.x;
                mv[mi] = eluf(x + mub[mi]) + 1.0f;
            }
            float2* dm = (float2*)(out + OUT_MU + (size_t)(pair0 + jj) * 10);
            #pragma unroll
            for (int k = 0; k < 5; k++) dm[k] = make_float2(mv[2*k], mv[2*k+1]);
        }
    }
}

// ================================================================ launch
extern "C" void kernel_launch(void* const* d_in, const int* in_sizes, int n_in,
                              void* d_out, int out_size) {
    const float* lig_s  = (const float*)d_in[0];
    const float* pro_s  = (const float*)d_in[1];
    const int*   donar  = (const int*)d_in[4];
    const int*   eidx   = (const int*)d_in[5];
    const float* mlp_w  = (const float*)d_in[6];
    const float* mlp_b  = (const float*)d_in[7];
    const float* mlp_g  = (const float*)d_in[8];
    const float* mlp_be = (const float*)d_in[9];
    const float* mlp_m  = (const float*)d_in[10];
    const float* mlp_v  = (const float*)d_in[11];
    const float* sel_w1 = (const float*)d_in[12];
    const float* sel_b1 = (const float*)d_in[13];
    const float* sel_g  = (const float*)d_in[14];
    const float* sel_be = (const float*)d_in[15];
    const float* sel_m  = (const float*)d_in[16];
    const float* sel_v  = (const float*)d_in[17];
    const float* sel_w2 = (const float*)d_in[18];
    const float* sel_b2 = (const float*)d_in[19];
    const float* pi_w   = (const float*)d_in[20];
    const float* pi_b   = (const float*)d_in[21];
    const float* sg_w   = (const float*)d_in[22];
    const float* sg_b   = (const float*)d_in[23];
    const float* mu_w   = (const float*)d_in[24];
    const float* mu_b   = (const float*)d_in[25];
    const float* at_w   = (const float*)d_in[26];
    const float* at_b   = (const float*)d_in[27];
    const float* bt_w   = (const float*)d_in[28];
    const float* bt_b   = (const float*)d_in[29];
    float* out = (float*)d_out;

    float *Lh, *ThT, *Ls, *Ts;
    cudaGetSymbolAddress((void**)&Lh,  g_Lh);
    cudaGetSymbolAddress((void**)&ThT, g_ThT);
    cudaGetSymbolAddress((void**)&Ls,  g_Ls);
    cudaGetSymbolAddress((void**)&Ts,  g_Ts);

    cudaFuncSetAttribute((const void*)back_kernel,
                         cudaFuncAttributeMaxDynamicSharedMemorySize, SMEM_MAIN);

    front_kernel<<<FRONT_BLOCKS, 256>>>(
        lig_s, pro_s, eidx,
        mlp_w, mlp_b, mlp_g, mlp_be, mlp_m, mlp_v,
        sel_w1, sel_b1, sel_g, sel_be, sel_m, sel_v,
        at_w, at_b, bt_w, bt_b,
        Lh, ThT, Ls, Ts, out);

    back_kernel<<<BACK_BLOCKS, 256, SMEM_MAIN>>>(
        Lh, ThT, Ls, Ts,
        pi_w, pi_b, sg_w, sg_b, mu_w, mu_b,
        donar, sel_w2, sel_b2, out);
}